// round 15
// baseline (speedup 1.0000x reference)
#include <cuda_runtime.h>
#include <math.h>
#include <stdint.h>

#define HID   3072
#define NH    24
#define HD    128
#define MLP   12288
#define SEQ   2048
#define W1N   21504              // 3*HID + MLP
#define MODN  9216
#define A2N   15360              // HID + MLP

// ---------------- scratch (device globals; no runtime alloc) ----------------
__device__ float g_mod [MODN];
__device__ float g_xmod[(size_t)SEQ * HID];
__device__ float g_h   [(size_t)SEQ * W1N];        // 176 MB
__device__ float g_qr  [(size_t)SEQ * HID];
__device__ float g_kr  [(size_t)SEQ * HID];
__device__ float g_sc  [(size_t)NH * SEQ * SEQ];   // 403 MB
__device__ float g_a2  [(size_t)SEQ * A2N];        // 126 MB

// ---------------- helpers ----------------
__device__ __forceinline__ float warpSum(float v) {
    #pragma unroll
    for (int o = 16; o; o >>= 1) v += __shfl_xor_sync(0xffffffffu, v, o);
    return v;
}

__device__ __forceinline__ float f2tf32f(float f) {
    uint32_t u;
    asm("cvt.rna.tf32.f32 %0, %1;" : "=r"(u) : "f"(f));
    return __uint_as_float(u);
}

// ---------------- 1) mod = silu(vec) @ mod_w + mod_b ----------------
__global__ __launch_bounds__(256) void k_mod(const float* __restrict__ vec,
                                             const float* __restrict__ mw,
                                             const float* __restrict__ mb) {
    __shared__ float s[HID];
    for (int i = threadIdx.x; i < HID; i += 256) {
        float v = vec[i];
        s[i] = v / (1.f + __expf(-v));
    }
    __syncthreads();
    int col = blockIdx.x * 256 + threadIdx.x;   // 9216 cols
    float acc = 0.f;
    for (int i = 0; i < HID; i++)
        acc = fmaf(s[i], mw[(size_t)i * MODN + col], acc);
    g_mod[col] = acc + mb[col];
}

// ---------------- 2) x_mod = (1+scale)*LN(x) + shift ----------------
__global__ __launch_bounds__(256) void k_lnmod(const float* __restrict__ x) {
    int row = blockIdx.x;
    const float* xr = x + (size_t)row * HID;
    int t = threadIdx.x;
    float v[12];
    float s = 0.f, q = 0.f;
    #pragma unroll
    for (int i = 0; i < 12; i++) {
        v[i] = xr[t + i * 256];
        s += v[i];
        q = fmaf(v[i], v[i], q);
    }
    __shared__ float sh1[8], sh2[8];
    s = warpSum(s); q = warpSum(q);
    if ((t & 31) == 0) { sh1[t >> 5] = s; sh2[t >> 5] = q; }
    __syncthreads();
    s = 0.f; q = 0.f;
    #pragma unroll
    for (int w = 0; w < 8; w++) { s += sh1[w]; q += sh2[w]; }
    float mu  = s * (1.f / HID);
    float var = q * (1.f / HID) - mu * mu;
    float inv = rsqrtf(var + 1e-6f);
    float* o = g_xmod + (size_t)row * HID;
    #pragma unroll
    for (int i = 0; i < 12; i++) {
        int c = t + i * 256;
        float xn = (v[i] - mu) * inv;
        o[c] = fmaf(1.f + g_mod[HID + c], xn, g_mod[c]);   // (1+scale)*xn + shift
    }
}

// ================= tf32 tensor-core GEMM (128x128x16, 4 warps, 64x64 warp tile) ====
// C(MxN) = A(MxK) * op(B),  op(B)=B (KxN, TB=false) or B^T (B is NxK, TB=true)
// 128 threads = 4 warps (2 in M x 2 in N), warp tile 64x64 via mma.m16n8k8 tf32.
// Double-buffered smem; conflict-free layouts:
//   As [2][BM][BK+4]  (M-major rows; STS.128; frag-load bank = gid*20+tig, distinct)
//   Bs TB=true : [2][BN][BK+4]  (same as A)
//   Bs TB=false: [2][BK][BN+8]  (frag-load bank = tig*8+gid, distinct)
// EPI: 0 = store, 1 = +bias, 2 = out = xres + gate*(acc+bias)
template<int EPI, bool TB>
__global__ __launch_bounds__(128, 2) void mma_gemm(
    int K,
    const float* __restrict__ A, int lda, long long sA,
    const float* __restrict__ B, int ldb, long long sB,
    float* __restrict__ C, int ldc, long long sC,
    const float* __restrict__ bias,
    const float* __restrict__ xres,
    const float* __restrict__ gate)
{
    constexpr int BM = 128, BN = 128, BK = 16;
    constexpr int AP = BK + 4;                 // 20 floats/row, 80B (16B aligned)
    constexpr int BROW = TB ? BN : BK;
    constexpr int BCOL = TB ? AP : (BN + 8);   // 136 floats/row, 544B (16B aligned)
    __shared__ __align__(16) float As[2][BM][AP];
    __shared__ __align__(16) float Bs[2][BROW][BCOL];

    A += (size_t)blockIdx.z * sA + (size_t)blockIdx.y * BM * lda;
    if (TB) B += (size_t)blockIdx.z * sB + (size_t)blockIdx.x * BN * ldb;
    else    B += (size_t)blockIdx.z * sB + (size_t)blockIdx.x * BN;

    const int tid  = threadIdx.x;
    const int lane = tid & 31, warp = tid >> 5;
    const int wm   = warp & 1;        // 2 warps in M (64 rows each)
    const int wn   = warp >> 1;       // 2 warps in N (64 cols each)
    const int gid  = lane >> 2;       // 0..7
    const int tig  = lane & 3;        // 0..3

    float acc[4][8][4] = {};
    float4 pa[4], pb[4];

    auto ldg = [&](int k0) {
        #pragma unroll
        for (int i = 0; i < 4; i++) {
            int f = tid + i * 128;
            pa[i] = *(const float4*)(A + (size_t)(f >> 2) * lda + k0 + (f & 3) * 4);
            if (TB)
                pb[i] = *(const float4*)(B + (size_t)(f >> 2) * ldb + k0 + (f & 3) * 4);
            else
                pb[i] = *(const float4*)(B + (size_t)(k0 + (f >> 5)) * ldb + (f & 31) * 4);
        }
    };
    auto sts = [&](int p) {
        #pragma unroll
        for (int i = 0; i < 4; i++) {
            int f = tid + i * 128;
            int r = f >> 2, c4 = (f & 3) * 4;
            float4 va = make_float4(f2tf32f(pa[i].x), f2tf32f(pa[i].y),
                                    f2tf32f(pa[i].z), f2tf32f(pa[i].w));
            *(float4*)&As[p][r][c4] = va;
            float4 vb = make_float4(f2tf32f(pb[i].x), f2tf32f(pb[i].y),
                                    f2tf32f(pb[i].z), f2tf32f(pb[i].w));
            if (TB) {
                *(float4*)&Bs[p][r][c4] = vb;
            } else {
                int k = f >> 5, n = (f & 31) * 4;
                *(float4*)&Bs[p][k][n] = vb;
            }
        }
    };

    ldg(0); sts(0);
    __syncthreads();

    int p = 0;
    for (int k0 = 0; k0 < K; k0 += BK) {
        const bool more = (k0 + BK < K);
        if (more) ldg(k0 + BK);

        #pragma unroll
        for (int kk = 0; kk < BK; kk += 8) {
            uint32_t af[4][4], bf[8][2];
            #pragma unroll
            for (int i = 0; i < 4; i++) {
                int rb = wm * 64 + i * 16 + gid;
                af[i][0] = __float_as_uint(As[p][rb    ][kk + tig    ]);
                af[i][1] = __float_as_uint(As[p][rb + 8][kk + tig    ]);
                af[i][2] = __float_as_uint(As[p][rb    ][kk + tig + 4]);
                af[i][3] = __float_as_uint(As[p][rb + 8][kk + tig + 4]);
            }
            #pragma unroll
            for (int j = 0; j < 8; j++) {
                int cb = wn * 64 + j * 8 + gid;
                if (TB) {
                    bf[j][0] = __float_as_uint(Bs[p][cb][kk + tig    ]);
                    bf[j][1] = __float_as_uint(Bs[p][cb][kk + tig + 4]);
                } else {
                    bf[j][0] = __float_as_uint(Bs[p][kk + tig    ][cb]);
                    bf[j][1] = __float_as_uint(Bs[p][kk + tig + 4][cb]);
                }
            }
            #pragma unroll
            for (int i = 0; i < 4; i++)
                #pragma unroll
                for (int j = 0; j < 8; j++)
                    asm volatile(
                        "mma.sync.aligned.m16n8k8.row.col.f32.tf32.tf32.f32 "
                        "{%0,%1,%2,%3},{%4,%5,%6,%7},{%8,%9},{%0,%1,%2,%3};"
                        : "+f"(acc[i][j][0]), "+f"(acc[i][j][1]),
                          "+f"(acc[i][j][2]), "+f"(acc[i][j][3])
                        : "r"(af[i][0]), "r"(af[i][1]), "r"(af[i][2]), "r"(af[i][3]),
                          "r"(bf[j][0]), "r"(bf[j][1]));
        }

        if (more) {
            sts(p ^ 1);
            __syncthreads();
            p ^= 1;
        }
    }

    // ---------------- epilogue ----------------
    C += (size_t)blockIdx.z * sC;
    const int rbase = blockIdx.y * BM + wm * 64;
    const int cbase = blockIdx.x * BN + wn * 64;
    #pragma unroll
    for (int i = 0; i < 4; i++) {
        #pragma unroll
        for (int j = 0; j < 8; j++) {
            int r = rbase + i * 16 + gid;
            int c = cbase + j * 8 + tig * 2;
            float v0 = acc[i][j][0], v1 = acc[i][j][1];
            float v2 = acc[i][j][2], v3 = acc[i][j][3];
            if (EPI == 1) {
                float b0 = bias[c], b1 = bias[c + 1];
                v0 += b0; v1 += b1; v2 += b0; v3 += b1;
            }
            size_t o0 = (size_t)r * ldc + c;
            size_t o1 = (size_t)(r + 8) * ldc + c;
            if (EPI == 2) {
                float b0 = bias[c], b1 = bias[c + 1];
                float gg0 = gate[c], gg1 = gate[c + 1];
                v0 = xres[o0]     + gg0 * (v0 + b0);
                v1 = xres[o0 + 1] + gg1 * (v1 + b1);
                v2 = xres[o1]     + gg0 * (v2 + b0);
                v3 = xres[o1 + 1] + gg1 * (v3 + b1);
            }
            *(float2*)(C + o0) = make_float2(v0, v1);
            *(float2*)(C + o1) = make_float2(v2, v3);
        }
    }
}

// ---------------- 4) q/k rmsnorm + rope (one warp per (row, head)) ----------------
__global__ __launch_bounds__(256) void k_qk(const float* __restrict__ pe,
                                            const float* __restrict__ qw,
                                            const float* __restrict__ kw) {
    int gw   = (blockIdx.x * 256 + threadIdx.x) >> 5;
    int lane = threadIdx.x & 31;
    if (gw >= SEQ * NH) return;
    int row = gw / NH, head = gw - row * NH;
    const float* per = pe + (size_t)row * 256;
    const float* src = g_h + (size_t)row * W1N + head * HD;
    float4 p0 = *(const float4*)(per + lane * 8);
    float4 p1 = *(const float4*)(per + lane * 8 + 4);

    // q
    {
        float4 xv = *(const float4*)(src + lane * 4);
        float ss = warpSum(xv.x*xv.x + xv.y*xv.y + xv.z*xv.z + xv.w*xv.w);
        float inv = rsqrtf(ss * (1.f / HD) + 1e-6f);
        float4 wv = *(const float4*)(qw + lane * 4);
        float n0 = xv.x*inv*wv.x, n1 = xv.y*inv*wv.y;
        float n2 = xv.z*inv*wv.z, n3 = xv.w*inv*wv.w;
        const float sc = 0.08838834764831845f;           // 128^-0.5 folded in
        float* d = g_qr + (size_t)row * HID + head * HD + lane * 4;
        d[0] = (p0.x*n0 + p0.y*n1) * sc;
        d[1] = (p0.z*n0 + p0.w*n1) * sc;
        d[2] = (p1.x*n2 + p1.y*n3) * sc;
        d[3] = (p1.z*n2 + p1.w*n3) * sc;
    }
    // k
    {
        float4 xv = *(const float4*)(src + HID + lane * 4);
        float ss = warpSum(xv.x*xv.x + xv.y*xv.y + xv.z*xv.z + xv.w*xv.w);
        float inv = rsqrtf(ss * (1.f / HD) + 1e-6f);
        float4 wv = *(const float4*)(kw + lane * 4);
        float n0 = xv.x*inv*wv.x, n1 = xv.y*inv*wv.y;
        float n2 = xv.z*inv*wv.z, n3 = xv.w*inv*wv.w;
        float* d = g_kr + (size_t)row * HID + head * HD + lane * 4;
        d[0] = p0.x*n0 + p0.y*n1;
        d[1] = p0.z*n0 + p0.w*n1;
        d[2] = p1.x*n2 + p1.y*n3;
        d[3] = p1.z*n2 + p1.w*n3;
    }
}

// ---------------- 6) row softmax over 2048 ----------------
__global__ __launch_bounds__(256) void k_softmax(float* __restrict__ S) {
    size_t base = (size_t)blockIdx.x * SEQ;
    int t = threadIdx.x;
    float v[8];
    float mx = -3.4e38f;
    #pragma unroll
    for (int i = 0; i < 8; i++) { v[i] = S[base + t + i * 256]; mx = fmaxf(mx, v[i]); }
    __shared__ float sh[8];
    #pragma unroll
    for (int o = 16; o; o >>= 1) mx = fmaxf(mx, __shfl_xor_sync(0xffffffffu, mx, o));
    if ((t & 31) == 0) sh[t >> 5] = mx;
    __syncthreads();
    mx = sh[0];
    #pragma unroll
    for (int w = 1; w < 8; w++) mx = fmaxf(mx, sh[w]);
    __syncthreads();
    float s = 0.f;
    #pragma unroll
    for (int i = 0; i < 8; i++) { v[i] = __expf(v[i] - mx); s += v[i]; }
    s = warpSum(s);
    if ((t & 31) == 0) sh[t >> 5] = s;
    __syncthreads();
    s = 0.f;
    #pragma unroll
    for (int w = 0; w < 8; w++) s += sh[w];
    float r = 1.f / s;
    #pragma unroll
    for (int i = 0; i < 8; i++) S[base + t + i * 256] = v[i] * r;
}

// ---------------- 7b) gelu(mlp) -> g_a2 columns [3072, 15360) ----------------
__global__ __launch_bounds__(256) void k_gelu() {
    int idx = blockIdx.x * 256 + threadIdx.x;      // total SEQ*MLP
    int m = idx / MLP, j = idx - m * MLP;
    float xv = g_h[(size_t)m * W1N + 3 * HID + j];
    float t = tanhf(0.7978845608028654f * (xv + 0.044715f * xv * xv * xv));
    g_a2[(size_t)m * A2N + HID + j] = 0.5f * xv * (1.f + t);
}

// ---------------- launch ----------------
extern "C" void kernel_launch(void* const* d_in, const int* in_sizes, int n_in,
                              void* d_out, int out_size) {
    const float* x   = (const float*)d_in[0];
    const float* vec = (const float*)d_in[1];
    const float* pe  = (const float*)d_in[2];
    const float* w1  = (const float*)d_in[3];
    const float* b1  = (const float*)d_in[4];
    const float* w2  = (const float*)d_in[5];
    const float* b2  = (const float*)d_in[6];
    const float* mw  = (const float*)d_in[7];
    const float* mb  = (const float*)d_in[8];
    const float* qw  = (const float*)d_in[9];
    const float* kw  = (const float*)d_in[10];
    float* out = (float*)d_out;

    float *p_mod, *p_xmod, *p_h, *p_qr, *p_kr, *p_sc, *p_a2;
    cudaGetSymbolAddress((void**)&p_mod,  g_mod);
    cudaGetSymbolAddress((void**)&p_xmod, g_xmod);
    cudaGetSymbolAddress((void**)&p_h,    g_h);
    cudaGetSymbolAddress((void**)&p_qr,   g_qr);
    cudaGetSymbolAddress((void**)&p_kr,   g_kr);
    cudaGetSymbolAddress((void**)&p_sc,   g_sc);
    cudaGetSymbolAddress((void**)&p_a2,   g_a2);

    // 1) modulation vector
    k_mod<<<MODN / 256, 256>>>(vec, mw, mb);
    // 2) layernorm + modulate
    k_lnmod<<<SEQ, 256>>>(x);
    // 3) h = x_mod @ w1 + b1   (tf32 tensor cores)
    {
        dim3 g(W1N / 128, SEQ / 128, 1);
        mma_gemm<1, false><<<g, 128>>>(HID,
            p_xmod, HID, 0, w1, W1N, 0, p_h, W1N, 0, b1, nullptr, nullptr);
    }
    // 4) q/k rmsnorm + rope (scale folded into q)
    k_qk<<<(SEQ * NH * 32) / 256, 256>>>(pe, qw, kw);
    // 5) scores = q @ k^T, per head   (tf32, B transposed)
    {
        dim3 g(SEQ / 128, SEQ / 128, NH);
        mma_gemm<0, true><<<g, 128>>>(HD,
            p_qr, HID, HD, p_kr, HID, HD, p_sc, SEQ, (long long)SEQ * SEQ,
            nullptr, nullptr, nullptr);
    }
    // 6) softmax over keys
    k_softmax<<<NH * SEQ, 256>>>(p_sc);
    // 7a) attn = P @ V  -> g_a2 columns [0, 3072)
    {
        dim3 g(1, SEQ / 128, NH);
        mma_gemm<0, false><<<g, 128>>>(SEQ,
            p_sc, SEQ, (long long)SEQ * SEQ,
            p_h + 2 * HID, W1N, HD,
            p_a2, A2N, HD, nullptr, nullptr, nullptr);
    }
    // 7b) gelu(mlp) -> g_a2 columns [3072, 15360)
    k_gelu<<<(SEQ * MLP) / 256, 256>>>();
    // 8) out = x + gate * ([attn | gelu(mlp)] @ w2 + b2)   (tf32)
    {
        dim3 g(HID / 128, SEQ / 128, 1);
        mma_gemm<2, false><<<g, 128>>>(A2N,
            p_a2, A2N, 0, w2, HID, 0, out, HID, 0, b2, x, p_mod + 2 * HID);
    }
}

// round 16
// speedup vs baseline: 1.0773x; 1.0773x over previous
#include <cuda_runtime.h>
#include <math.h>
#include <stdint.h>

#define HID   3072
#define NH    24
#define HD    128
#define MLP   12288
#define SEQ   2048
#define W1N   21504              // 3*HID + MLP
#define MODN  9216
#define A2N   15360              // HID + MLP

// ---------------- scratch (device globals; no runtime alloc) ----------------
__device__ float g_mod [MODN];
__device__ float g_xmod[(size_t)SEQ * HID];
__device__ float g_h   [(size_t)SEQ * W1N];        // 176 MB
__device__ float g_qr  [(size_t)SEQ * HID];
__device__ float g_kr  [(size_t)SEQ * HID];
__device__ float g_sc  [(size_t)NH * SEQ * SEQ];   // 403 MB
__device__ float g_a2  [(size_t)SEQ * A2N];        // 126 MB
__device__ float g_w1t [(size_t)HID * W1N];        // 264 MB tf32-rounded w1
__device__ float g_w2t [(size_t)A2N * HID];        // 189 MB tf32-rounded w2

// ---------------- helpers ----------------
__device__ __forceinline__ float warpSum(float v) {
    #pragma unroll
    for (int o = 16; o; o >>= 1) v += __shfl_xor_sync(0xffffffffu, v, o);
    return v;
}

__device__ __forceinline__ float f2tf32f(float f) {
    uint32_t u;
    asm("cvt.rna.tf32.f32 %0, %1;" : "=r"(u) : "f"(f));
    return __uint_as_float(u);
}

#define CP16(dst, src) \
    asm volatile("cp.async.cg.shared.global [%0], [%1], 16;" :: "r"(dst), "l"(src))
#define CP_COMMIT() asm volatile("cp.async.commit_group;")
#define CP_WAIT0()  asm volatile("cp.async.wait_group 0;")

// ---------------- 0) tf32 pre-rounding of weights ----------------
__global__ __launch_bounds__(256) void k_cvt(const float* __restrict__ src,
                                             float* __restrict__ dst) {
    size_t i = ((size_t)blockIdx.x * 256 + threadIdx.x) * 4;
    float4 v = *(const float4*)(src + i);
    v.x = f2tf32f(v.x); v.y = f2tf32f(v.y);
    v.z = f2tf32f(v.z); v.w = f2tf32f(v.w);
    *(float4*)(dst + i) = v;
}

// ---------------- 1) mod = silu(vec) @ mod_w + mod_b ----------------
__global__ __launch_bounds__(256) void k_mod(const float* __restrict__ vec,
                                             const float* __restrict__ mw,
                                             const float* __restrict__ mb) {
    __shared__ float s[HID];
    for (int i = threadIdx.x; i < HID; i += 256) {
        float v = vec[i];
        s[i] = v / (1.f + __expf(-v));
    }
    __syncthreads();
    int col = blockIdx.x * 256 + threadIdx.x;   // 9216 cols
    float acc = 0.f;
    for (int i = 0; i < HID; i++)
        acc = fmaf(s[i], mw[(size_t)i * MODN + col], acc);
    g_mod[col] = acc + mb[col];
}

// ---------------- 2) x_mod = (1+scale)*LN(x) + shift  (tf32-rounded out) ----
__global__ __launch_bounds__(256) void k_lnmod(const float* __restrict__ x) {
    int row = blockIdx.x;
    const float* xr = x + (size_t)row * HID;
    int t = threadIdx.x;
    float v[12];
    float s = 0.f, q = 0.f;
    #pragma unroll
    for (int i = 0; i < 12; i++) {
        v[i] = xr[t + i * 256];
        s += v[i];
        q = fmaf(v[i], v[i], q);
    }
    __shared__ float sh1[8], sh2[8];
    s = warpSum(s); q = warpSum(q);
    if ((t & 31) == 0) { sh1[t >> 5] = s; sh2[t >> 5] = q; }
    __syncthreads();
    s = 0.f; q = 0.f;
    #pragma unroll
    for (int w = 0; w < 8; w++) { s += sh1[w]; q += sh2[w]; }
    float mu  = s * (1.f / HID);
    float var = q * (1.f / HID) - mu * mu;
    float inv = rsqrtf(var + 1e-6f);
    float* o = g_xmod + (size_t)row * HID;
    #pragma unroll
    for (int i = 0; i < 12; i++) {
        int c = t + i * 256;
        float xn = (v[i] - mu) * inv;
        o[c] = f2tf32f(fmaf(1.f + g_mod[HID + c], xn, g_mod[c]));
    }
}

// ============ tf32 tensor-core GEMM (128x128x16, 4 warps, cp.async) =========
// All operands must already be tf32-rounded (rna) in global memory.
// C(MxN) = A(MxK) * op(B),  op(B)=B (KxN, TB=false) or B^T (B is NxK, TB=true)
// EPI: 0 = store rounded, 1 = +bias (rounded), 2 = out = xres + gate*(acc+bias)
template<int EPI, bool TB>
__global__ __launch_bounds__(128, 2) void mma_gemm(
    int K,
    const float* __restrict__ A, int lda, long long sA,
    const float* __restrict__ B, int ldb, long long sB,
    float* __restrict__ C, int ldc, long long sC,
    const float* __restrict__ bias,
    const float* __restrict__ xres,
    const float* __restrict__ gate)
{
    constexpr int BM = 128, BN = 128, BK = 16;
    constexpr int AP = BK + 4;                 // 20 floats/row (80B, 16B-mult)
    constexpr int BROW = TB ? BN : BK;
    constexpr int BCOL = TB ? AP : (BN + 8);   // 136 floats/row (544B)
    __shared__ __align__(16) float As[2][BM][AP];
    __shared__ __align__(16) float Bs[2][BROW][BCOL];

    A += (size_t)blockIdx.z * sA + (size_t)blockIdx.y * BM * lda;
    if (TB) B += (size_t)blockIdx.z * sB + (size_t)blockIdx.x * BN * ldb;
    else    B += (size_t)blockIdx.z * sB + (size_t)blockIdx.x * BN;

    const int tid  = threadIdx.x;
    const int lane = tid & 31, warp = tid >> 5;
    const int wm   = warp & 1;        // 2 warps in M (64 rows each)
    const int wn   = warp >> 1;       // 2 warps in N (64 cols each)
    const int gid  = lane >> 2;       // 0..7
    const int tig  = lane & 3;        // 0..3

    float acc[4][8][4] = {};

    auto stage = [&](int p, int k0) {
        #pragma unroll
        for (int i = 0; i < 4; i++) {
            int f = tid + i * 128;
            int r = f >> 2, c4 = (f & 3) * 4;
            uint32_t da = (uint32_t)__cvta_generic_to_shared(&As[p][r][c4]);
            CP16(da, A + (size_t)r * lda + k0 + c4);
            if (TB) {
                uint32_t db = (uint32_t)__cvta_generic_to_shared(&Bs[p][r][c4]);
                CP16(db, B + (size_t)r * ldb + k0 + c4);
            } else {
                int k = f >> 5, n = (f & 31) * 4;
                uint32_t db = (uint32_t)__cvta_generic_to_shared(&Bs[p][k][n]);
                CP16(db, B + (size_t)(k0 + k) * ldb + n);
            }
        }
        CP_COMMIT();
    };

    stage(0, 0);
    CP_WAIT0();
    __syncthreads();

    int p = 0;
    for (int k0 = 0; k0 < K; k0 += BK) {
        const bool more = (k0 + BK < K);
        if (more) stage(p ^ 1, k0 + BK);

        #pragma unroll
        for (int kk = 0; kk < BK; kk += 8) {
            uint32_t af[4][4], bf[8][2];
            #pragma unroll
            for (int i = 0; i < 4; i++) {
                int rb = wm * 64 + i * 16 + gid;
                af[i][0] = __float_as_uint(As[p][rb    ][kk + tig    ]);
                af[i][1] = __float_as_uint(As[p][rb + 8][kk + tig    ]);
                af[i][2] = __float_as_uint(As[p][rb    ][kk + tig + 4]);
                af[i][3] = __float_as_uint(As[p][rb + 8][kk + tig + 4]);
            }
            #pragma unroll
            for (int j = 0; j < 8; j++) {
                int cb = wn * 64 + j * 8 + gid;
                if (TB) {
                    bf[j][0] = __float_as_uint(Bs[p][cb][kk + tig    ]);
                    bf[j][1] = __float_as_uint(Bs[p][cb][kk + tig + 4]);
                } else {
                    bf[j][0] = __float_as_uint(Bs[p][kk + tig    ][cb]);
                    bf[j][1] = __float_as_uint(Bs[p][kk + tig + 4][cb]);
                }
            }
            #pragma unroll
            for (int i = 0; i < 4; i++)
                #pragma unroll
                for (int j = 0; j < 8; j++)
                    asm volatile(
                        "mma.sync.aligned.m16n8k8.row.col.f32.tf32.tf32.f32 "
                        "{%0,%1,%2,%3},{%4,%5,%6,%7},{%8,%9},{%0,%1,%2,%3};"
                        : "+f"(acc[i][j][0]), "+f"(acc[i][j][1]),
                          "+f"(acc[i][j][2]), "+f"(acc[i][j][3])
                        : "r"(af[i][0]), "r"(af[i][1]), "r"(af[i][2]), "r"(af[i][3]),
                          "r"(bf[j][0]), "r"(bf[j][1]));
        }

        if (more) {
            CP_WAIT0();
            __syncthreads();
            p ^= 1;
        }
    }

    // ---------------- epilogue ----------------
    C += (size_t)blockIdx.z * sC;
    const int rbase = blockIdx.y * BM + wm * 64;
    const int cbase = blockIdx.x * BN + wn * 64;
    #pragma unroll
    for (int i = 0; i < 4; i++) {
        #pragma unroll
        for (int j = 0; j < 8; j++) {
            int r = rbase + i * 16 + gid;
            int c = cbase + j * 8 + tig * 2;
            float v0 = acc[i][j][0], v1 = acc[i][j][1];
            float v2 = acc[i][j][2], v3 = acc[i][j][3];
            size_t o0 = (size_t)r * ldc + c;
            size_t o1 = (size_t)(r + 8) * ldc + c;
            if (EPI == 1) {
                float b0 = bias[c], b1 = bias[c + 1];
                v0 += b0; v1 += b1; v2 += b0; v3 += b1;
            }
            if (EPI == 2) {
                float b0 = bias[c], b1 = bias[c + 1];
                float gg0 = gate[c], gg1 = gate[c + 1];
                v0 = xres[o0]     + gg0 * (v0 + b0);
                v1 = xres[o0 + 1] + gg1 * (v1 + b1);
                v2 = xres[o1]     + gg0 * (v2 + b0);
                v3 = xres[o1 + 1] + gg1 * (v3 + b1);
            } else {
                v0 = f2tf32f(v0); v1 = f2tf32f(v1);
                v2 = f2tf32f(v2); v3 = f2tf32f(v3);
            }
            *(float2*)(C + o0) = make_float2(v0, v1);
            *(float2*)(C + o1) = make_float2(v2, v3);
        }
    }
}

// ---------------- 4) q/k rmsnorm + rope (one warp per (row, head)) ----------
__global__ __launch_bounds__(256) void k_qk(const float* __restrict__ pe,
                                            const float* __restrict__ qw,
                                            const float* __restrict__ kw) {
    int gw   = (blockIdx.x * 256 + threadIdx.x) >> 5;
    int lane = threadIdx.x & 31;
    if (gw >= SEQ * NH) return;
    int row = gw / NH, head = gw - row * NH;
    const float* per = pe + (size_t)row * 256;
    const float* src = g_h + (size_t)row * W1N + head * HD;
    float4 p0 = *(const float4*)(per + lane * 8);
    float4 p1 = *(const float4*)(per + lane * 8 + 4);

    // q
    {
        float4 xv = *(const float4*)(src + lane * 4);
        float ss = warpSum(xv.x*xv.x + xv.y*xv.y + xv.z*xv.z + xv.w*xv.w);
        float inv = rsqrtf(ss * (1.f / HD) + 1e-6f);
        float4 wv = *(const float4*)(qw + lane * 4);
        float n0 = xv.x*inv*wv.x, n1 = xv.y*inv*wv.y;
        float n2 = xv.z*inv*wv.z, n3 = xv.w*inv*wv.w;
        const float sc = 0.08838834764831845f;           // 128^-0.5 folded in
        float* d = g_qr + (size_t)row * HID + head * HD + lane * 4;
        d[0] = f2tf32f((p0.x*n0 + p0.y*n1) * sc);
        d[1] = f2tf32f((p0.z*n0 + p0.w*n1) * sc);
        d[2] = f2tf32f((p1.x*n2 + p1.y*n3) * sc);
        d[3] = f2tf32f((p1.z*n2 + p1.w*n3) * sc);
    }
    // k
    {
        float4 xv = *(const float4*)(src + HID + lane * 4);
        float ss = warpSum(xv.x*xv.x + xv.y*xv.y + xv.z*xv.z + xv.w*xv.w);
        float inv = rsqrtf(ss * (1.f / HD) + 1e-6f);
        float4 wv = *(const float4*)(kw + lane * 4);
        float n0 = xv.x*inv*wv.x, n1 = xv.y*inv*wv.y;
        float n2 = xv.z*inv*wv.z, n3 = xv.w*inv*wv.w;
        float* d = g_kr + (size_t)row * HID + head * HD + lane * 4;
        d[0] = f2tf32f(p0.x*n0 + p0.y*n1);
        d[1] = f2tf32f(p0.z*n0 + p0.w*n1);
        d[2] = f2tf32f(p1.x*n2 + p1.y*n3);
        d[3] = f2tf32f(p1.z*n2 + p1.w*n3);
    }
}

// ---------------- 6) row softmax over 2048 (tf32-rounded out) ---------------
__global__ __launch_bounds__(256) void k_softmax(float* __restrict__ S) {
    size_t base = (size_t)blockIdx.x * SEQ;
    int t = threadIdx.x;
    float v[8];
    float mx = -3.4e38f;
    #pragma unroll
    for (int i = 0; i < 8; i++) { v[i] = S[base + t + i * 256]; mx = fmaxf(mx, v[i]); }
    __shared__ float sh[8];
    #pragma unroll
    for (int o = 16; o; o >>= 1) mx = fmaxf(mx, __shfl_xor_sync(0xffffffffu, mx, o));
    if ((t & 31) == 0) sh[t >> 5] = mx;
    __syncthreads();
    mx = sh[0];
    #pragma unroll
    for (int w = 1; w < 8; w++) mx = fmaxf(mx, sh[w]);
    __syncthreads();
    float s = 0.f;
    #pragma unroll
    for (int i = 0; i < 8; i++) { v[i] = __expf(v[i] - mx); s += v[i]; }
    s = warpSum(s);
    if ((t & 31) == 0) sh[t >> 5] = s;
    __syncthreads();
    s = 0.f;
    #pragma unroll
    for (int w = 0; w < 8; w++) s += sh[w];
    float r = 1.f / s;
    #pragma unroll
    for (int i = 0; i < 8; i++) S[base + t + i * 256] = f2tf32f(v[i] * r);
}

// ---------------- 7b) gelu(mlp) -> g_a2 columns [3072, 15360) ---------------
__global__ __launch_bounds__(256) void k_gelu() {
    int idx = blockIdx.x * 256 + threadIdx.x;      // total SEQ*MLP
    int m = idx / MLP, j = idx - m * MLP;
    float xv = g_h[(size_t)m * W1N + 3 * HID + j];
    float t = tanhf(0.7978845608028654f * (xv + 0.044715f * xv * xv * xv));
    g_a2[(size_t)m * A2N + HID + j] = f2tf32f(0.5f * xv * (1.f + t));
}

// ---------------- launch ----------------
extern "C" void kernel_launch(void* const* d_in, const int* in_sizes, int n_in,
                              void* d_out, int out_size) {
    const float* x   = (const float*)d_in[0];
    const float* vec = (const float*)d_in[1];
    const float* pe  = (const float*)d_in[2];
    const float* w1  = (const float*)d_in[3];
    const float* b1  = (const float*)d_in[4];
    const float* w2  = (const float*)d_in[5];
    const float* b2  = (const float*)d_in[6];
    const float* mw  = (const float*)d_in[7];
    const float* mb  = (const float*)d_in[8];
    const float* qw  = (const float*)d_in[9];
    const float* kw  = (const float*)d_in[10];
    float* out = (float*)d_out;

    float *p_mod, *p_xmod, *p_h, *p_qr, *p_kr, *p_sc, *p_a2, *p_w1t, *p_w2t;
    cudaGetSymbolAddress((void**)&p_mod,  g_mod);
    cudaGetSymbolAddress((void**)&p_xmod, g_xmod);
    cudaGetSymbolAddress((void**)&p_h,    g_h);
    cudaGetSymbolAddress((void**)&p_qr,   g_qr);
    cudaGetSymbolAddress((void**)&p_kr,   g_kr);
    cudaGetSymbolAddress((void**)&p_sc,   g_sc);
    cudaGetSymbolAddress((void**)&p_a2,   g_a2);
    cudaGetSymbolAddress((void**)&p_w1t,  g_w1t);
    cudaGetSymbolAddress((void**)&p_w2t,  g_w2t);

    // 0) pre-round weights to tf32 (once per launch)
    k_cvt<<<(size_t)HID * W1N / 1024, 256>>>(w1, p_w1t);
    k_cvt<<<(size_t)A2N * HID / 1024, 256>>>(w2, p_w2t);
    // 1) modulation vector
    k_mod<<<MODN / 256, 256>>>(vec, mw, mb);
    // 2) layernorm + modulate (tf32-rounded)
    k_lnmod<<<SEQ, 256>>>(x);
    // 3) h = x_mod @ w1 + b1   (tf32 tensor cores, cp.async pipeline)
    {
        dim3 g(W1N / 128, SEQ / 128, 1);
        mma_gemm<1, false><<<g, 128>>>(HID,
            p_xmod, HID, 0, p_w1t, W1N, 0, p_h, W1N, 0, b1, nullptr, nullptr);
    }
    // 4) q/k rmsnorm + rope (scale folded into q, tf32-rounded)
    k_qk<<<(SEQ * NH * 32) / 256, 256>>>(pe, qw, kw);
    // 5) scores = q @ k^T, per head   (tf32, B transposed)
    {
        dim3 g(SEQ / 128, SEQ / 128, NH);
        mma_gemm<0, true><<<g, 128>>>(HD,
            p_qr, HID, HD, p_kr, HID, HD, p_sc, SEQ, (long long)SEQ * SEQ,
            nullptr, nullptr, nullptr);
    }
    // 6) softmax over keys (tf32-rounded)
    k_softmax<<<NH * SEQ, 256>>>(p_sc);
    // 7a) attn = P @ V  -> g_a2 columns [0, 3072)
    {
        dim3 g(1, SEQ / 128, NH);
        mma_gemm<0, false><<<g, 128>>>(SEQ,
            p_sc, SEQ, (long long)SEQ * SEQ,
            p_h + 2 * HID, W1N, HD,
            p_a2, A2N, HD, nullptr, nullptr, nullptr);
    }
    // 7b) gelu(mlp) -> g_a2 columns [3072, 15360)
    k_gelu<<<(SEQ * MLP) / 256, 256>>>();
    // 8) out = x + gate * ([attn | gelu(mlp)] @ w2 + b2)   (tf32)
    {
        dim3 g(HID / 128, SEQ / 128, 1);
        mma_gemm<2, false><<<g, 128>>>(A2N,
            p_a2, A2N, 0, p_w2t, HID, 0, out, HID, 0, b2, x, p_mod + 2 * HID);
    }
}

// round 17
// speedup vs baseline: 1.1515x; 1.0689x over previous
#include <cuda_runtime.h>
#include <math.h>
#include <stdint.h>

#define HID   3072
#define NH    24
#define HD    128
#define MLP   12288
#define SEQ   2048
#define W1N   21504              // 3*HID + MLP
#define MODN  9216
#define A2N   15360              // HID + MLP

// ---------------- scratch (device globals; no runtime alloc) ----------------
__device__ float g_mod [MODN];
__device__ float g_xmod[(size_t)SEQ * HID];
__device__ float g_h   [(size_t)SEQ * W1N];        // qkv lives in first 9216 cols
__device__ float g_qr  [(size_t)SEQ * HID];
__device__ float g_kr  [(size_t)SEQ * HID];
__device__ float g_sc  [(size_t)NH * SEQ * SEQ];   // 403 MB
__device__ float g_a2  [(size_t)SEQ * A2N];        // 126 MB
__device__ float g_w1t [(size_t)HID * W1N];        // tf32-rounded w1
__device__ float g_w2t [(size_t)A2N * HID];        // tf32-rounded w2

// ---------------- helpers ----------------
__device__ __forceinline__ float warpSum(float v) {
    #pragma unroll
    for (int o = 16; o; o >>= 1) v += __shfl_xor_sync(0xffffffffu, v, o);
    return v;
}

__device__ __forceinline__ float f2tf32f(float f) {
    uint32_t u;
    asm("cvt.rna.tf32.f32 %0, %1;" : "=r"(u) : "f"(f));
    return __uint_as_float(u);
}

#define CP16(dst, src) \
    asm volatile("cp.async.cg.shared.global [%0], [%1], 16;" :: "r"(dst), "l"(src))
#define CP_COMMIT() asm volatile("cp.async.commit_group;")
#define CP_WAIT2()  asm volatile("cp.async.wait_group 2;")

// ---------------- 0) tf32 pre-rounding of weights ----------------
__global__ __launch_bounds__(256) void k_cvt(const float* __restrict__ src,
                                             float* __restrict__ dst) {
    size_t i = ((size_t)blockIdx.x * 256 + threadIdx.x) * 4;
    float4 v = *(const float4*)(src + i);
    v.x = f2tf32f(v.x); v.y = f2tf32f(v.y);
    v.z = f2tf32f(v.z); v.w = f2tf32f(v.w);
    *(float4*)(dst + i) = v;
}

// ---------------- 1) mod = silu(vec) @ mod_w + mod_b ----------------
__global__ __launch_bounds__(256) void k_mod(const float* __restrict__ vec,
                                             const float* __restrict__ mw,
                                             const float* __restrict__ mb) {
    __shared__ float s[HID];
    for (int i = threadIdx.x; i < HID; i += 256) {
        float v = vec[i];
        s[i] = v / (1.f + __expf(-v));
    }
    __syncthreads();
    int col = blockIdx.x * 256 + threadIdx.x;   // 9216 cols
    float acc = 0.f;
    for (int i = 0; i < HID; i++)
        acc = fmaf(s[i], mw[(size_t)i * MODN + col], acc);
    g_mod[col] = acc + mb[col];
}

// ---------------- 2) x_mod = (1+scale)*LN(x) + shift  (tf32-rounded out) ----
__global__ __launch_bounds__(256) void k_lnmod(const float* __restrict__ x) {
    int row = blockIdx.x;
    const float* xr = x + (size_t)row * HID;
    int t = threadIdx.x;
    float v[12];
    float s = 0.f, q = 0.f;
    #pragma unroll
    for (int i = 0; i < 12; i++) {
        v[i] = xr[t + i * 256];
        s += v[i];
        q = fmaf(v[i], v[i], q);
    }
    __shared__ float sh1[8], sh2[8];
    s = warpSum(s); q = warpSum(q);
    if ((t & 31) == 0) { sh1[t >> 5] = s; sh2[t >> 5] = q; }
    __syncthreads();
    s = 0.f; q = 0.f;
    #pragma unroll
    for (int w = 0; w < 8; w++) { s += sh1[w]; q += sh2[w]; }
    float mu  = s * (1.f / HID);
    float var = q * (1.f / HID) - mu * mu;
    float inv = rsqrtf(var + 1e-6f);
    float* o = g_xmod + (size_t)row * HID;
    #pragma unroll
    for (int i = 0; i < 12; i++) {
        int c = t + i * 256;
        float xn = (v[i] - mu) * inv;
        o[c] = f2tf32f(fmaf(1.f + g_mod[HID + c], xn, g_mod[c]));
    }
}

// ===== tf32 tensor-core GEMM (128x128x16, 4 warps, 4-stage cp.async ring) ====
// All operands must already be tf32-rounded (rna) in global memory.
// C(MxN) = A(MxK) * op(B),  op(B)=B (KxN, TB=false) or B^T (B is NxK, TB=true)
// EPI: 0 = store rounded, 1 = +bias rounded, 2 = out = xres + gate*(acc+bias),
//      3 = gelu(acc+bias) rounded
template<int EPI, bool TB>
__global__ __launch_bounds__(128, 2) void mma_gemm(
    int K,
    const float* __restrict__ A, int lda, long long sA,
    const float* __restrict__ B, int ldb, long long sB,
    float* __restrict__ C, int ldc, long long sC,
    const float* __restrict__ bias,
    const float* __restrict__ xres,
    const float* __restrict__ gate)
{
    constexpr int BM = 128, BN = 128, BK = 16, NS = 4;
    constexpr int AP = BK + 4;                 // 20 floats/row (80B)
    constexpr int BROW = TB ? BN : BK;
    constexpr int BCOL = TB ? AP : (BN + 8);   // 136 floats/row (544B)
    extern __shared__ float smem[];
    float* Asm = smem;                          // [NS][BM][AP]
    float* Bsm = smem + NS * BM * AP;           // [NS][BROW][BCOL]

    A += (size_t)blockIdx.z * sA + (size_t)blockIdx.y * BM * lda;
    if (TB) B += (size_t)blockIdx.z * sB + (size_t)blockIdx.x * BN * ldb;
    else    B += (size_t)blockIdx.z * sB + (size_t)blockIdx.x * BN;

    const int tid  = threadIdx.x;
    const int lane = tid & 31, warp = tid >> 5;
    const int wm   = warp & 1;        // 2 warps in M (64 rows each)
    const int wn   = warp >> 1;       // 2 warps in N (64 cols each)
    const int gid  = lane >> 2;       // 0..7
    const int tig  = lane & 3;        // 0..3

    float acc[4][8][4] = {};

    auto stage = [&](int s, int k0) {
        #pragma unroll
        for (int i = 0; i < 4; i++) {
            int f = tid + i * 128;
            int r = f >> 2, c4 = (f & 3) * 4;
            uint32_t da = (uint32_t)__cvta_generic_to_shared(
                &Asm[((size_t)s * BM + r) * AP + c4]);
            CP16(da, A + (size_t)r * lda + k0 + c4);
            if (TB) {
                uint32_t db = (uint32_t)__cvta_generic_to_shared(
                    &Bsm[((size_t)s * BROW + r) * BCOL + c4]);
                CP16(db, B + (size_t)r * ldb + k0 + c4);
            } else {
                int k = f >> 5, n = (f & 31) * 4;
                uint32_t db = (uint32_t)__cvta_generic_to_shared(
                    &Bsm[((size_t)s * BROW + k) * BCOL + n]);
                CP16(db, B + (size_t)(k0 + k) * ldb + n);
            }
        }
        CP_COMMIT();
    };

    const int T = K / BK;
    #pragma unroll
    for (int s = 0; s < 3; s++) {
        if (s < T) stage(s, s * BK); else CP_COMMIT();
    }

    for (int t = 0; t < T; t++) {
        CP_WAIT2();              // group t complete (2 newer groups may be in flight)
        __syncthreads();         // data visible; everyone done reading slot (t-1)&3
        if (t + 3 < T) stage((t + 3) & 3, (t + 3) * BK);
        else           CP_COMMIT();          // keep group count uniform
        const int p = t & 3;
        const float* Ap = &Asm[(size_t)p * BM * AP];
        const float* Bp = &Bsm[(size_t)p * BROW * BCOL];

        #pragma unroll
        for (int kk = 0; kk < BK; kk += 8) {
            uint32_t af[4][4], bf[8][2];
            #pragma unroll
            for (int i = 0; i < 4; i++) {
                int rb = wm * 64 + i * 16 + gid;
                af[i][0] = __float_as_uint(Ap[(size_t)(rb    ) * AP + kk + tig    ]);
                af[i][1] = __float_as_uint(Ap[(size_t)(rb + 8) * AP + kk + tig    ]);
                af[i][2] = __float_as_uint(Ap[(size_t)(rb    ) * AP + kk + tig + 4]);
                af[i][3] = __float_as_uint(Ap[(size_t)(rb + 8) * AP + kk + tig + 4]);
            }
            #pragma unroll
            for (int j = 0; j < 8; j++) {
                int cb = wn * 64 + j * 8 + gid;
                if (TB) {
                    bf[j][0] = __float_as_uint(Bp[(size_t)cb * BCOL + kk + tig    ]);
                    bf[j][1] = __float_as_uint(Bp[(size_t)cb * BCOL + kk + tig + 4]);
                } else {
                    bf[j][0] = __float_as_uint(Bp[(size_t)(kk + tig    ) * BCOL + cb]);
                    bf[j][1] = __float_as_uint(Bp[(size_t)(kk + tig + 4) * BCOL + cb]);
                }
            }
            #pragma unroll
            for (int i = 0; i < 4; i++)
                #pragma unroll
                for (int j = 0; j < 8; j++)
                    asm volatile(
                        "mma.sync.aligned.m16n8k8.row.col.f32.tf32.tf32.f32 "
                        "{%0,%1,%2,%3},{%4,%5,%6,%7},{%8,%9},{%0,%1,%2,%3};"
                        : "+f"(acc[i][j][0]), "+f"(acc[i][j][1]),
                          "+f"(acc[i][j][2]), "+f"(acc[i][j][3])
                        : "r"(af[i][0]), "r"(af[i][1]), "r"(af[i][2]), "r"(af[i][3]),
                          "r"(bf[j][0]), "r"(bf[j][1]));
        }
    }

    // ---------------- epilogue ----------------
    C += (size_t)blockIdx.z * sC;
    const int rbase = blockIdx.y * BM + wm * 64;
    const int cbase = blockIdx.x * BN + wn * 64;
    #pragma unroll
    for (int i = 0; i < 4; i++) {
        #pragma unroll
        for (int j = 0; j < 8; j++) {
            int r = rbase + i * 16 + gid;
            int c = cbase + j * 8 + tig * 2;
            float v0 = acc[i][j][0], v1 = acc[i][j][1];
            float v2 = acc[i][j][2], v3 = acc[i][j][3];
            size_t o0 = (size_t)r * ldc + c;
            size_t o1 = (size_t)(r + 8) * ldc + c;
            if (EPI == 1 || EPI == 3) {
                float b0 = bias[c], b1 = bias[c + 1];
                v0 += b0; v1 += b1; v2 += b0; v3 += b1;
            }
            if (EPI == 3) {
                #define GELU(x) (0.5f * (x) * (1.f + tanhf(0.7978845608028654f * \
                                 ((x) + 0.044715f * (x) * (x) * (x)))))
                v0 = GELU(v0); v1 = GELU(v1); v2 = GELU(v2); v3 = GELU(v3);
                #undef GELU
            }
            if (EPI == 2) {
                float b0 = bias[c], b1 = bias[c + 1];
                float gg0 = gate[c], gg1 = gate[c + 1];
                v0 = xres[o0]     + gg0 * (v0 + b0);
                v1 = xres[o0 + 1] + gg1 * (v1 + b1);
                v2 = xres[o1]     + gg0 * (v2 + b0);
                v3 = xres[o1 + 1] + gg1 * (v3 + b1);
            } else {
                v0 = f2tf32f(v0); v1 = f2tf32f(v1);
                v2 = f2tf32f(v2); v3 = f2tf32f(v3);
            }
            *(float2*)(C + o0) = make_float2(v0, v1);
            *(float2*)(C + o1) = make_float2(v2, v3);
        }
    }
}

// ---------------- 4) q/k rmsnorm + rope (one warp per (row, head)) ----------
__global__ __launch_bounds__(256) void k_qk(const float* __restrict__ pe,
                                            const float* __restrict__ qw,
                                            const float* __restrict__ kw) {
    int gw   = (blockIdx.x * 256 + threadIdx.x) >> 5;
    int lane = threadIdx.x & 31;
    if (gw >= SEQ * NH) return;
    int row = gw / NH, head = gw - row * NH;
    const float* per = pe + (size_t)row * 256;
    const float* src = g_h + (size_t)row * W1N + head * HD;
    float4 p0 = *(const float4*)(per + lane * 8);
    float4 p1 = *(const float4*)(per + lane * 8 + 4);

    // q
    {
        float4 xv = *(const float4*)(src + lane * 4);
        float ss = warpSum(xv.x*xv.x + xv.y*xv.y + xv.z*xv.z + xv.w*xv.w);
        float inv = rsqrtf(ss * (1.f / HD) + 1e-6f);
        float4 wv = *(const float4*)(qw + lane * 4);
        float n0 = xv.x*inv*wv.x, n1 = xv.y*inv*wv.y;
        float n2 = xv.z*inv*wv.z, n3 = xv.w*inv*wv.w;
        const float sc = 0.08838834764831845f;           // 128^-0.5 folded in
        float* d = g_qr + (size_t)row * HID + head * HD + lane * 4;
        d[0] = f2tf32f((p0.x*n0 + p0.y*n1) * sc);
        d[1] = f2tf32f((p0.z*n0 + p0.w*n1) * sc);
        d[2] = f2tf32f((p1.x*n2 + p1.y*n3) * sc);
        d[3] = f2tf32f((p1.z*n2 + p1.w*n3) * sc);
    }
    // k
    {
        float4 xv = *(const float4*)(src + HID + lane * 4);
        float ss = warpSum(xv.x*xv.x + xv.y*xv.y + xv.z*xv.z + xv.w*xv.w);
        float inv = rsqrtf(ss * (1.f / HD) + 1e-6f);
        float4 wv = *(const float4*)(kw + lane * 4);
        float n0 = xv.x*inv*wv.x, n1 = xv.y*inv*wv.y;
        float n2 = xv.z*inv*wv.z, n3 = xv.w*inv*wv.w;
        float* d = g_kr + (size_t)row * HID + head * HD + lane * 4;
        d[0] = f2tf32f(p0.x*n0 + p0.y*n1);
        d[1] = f2tf32f(p0.z*n0 + p0.w*n1);
        d[2] = f2tf32f(p1.x*n2 + p1.y*n3);
        d[3] = f2tf32f(p1.z*n2 + p1.w*n3);
    }
}

// ---------------- 6) row softmax over 2048 (tf32-rounded out) ---------------
__global__ __launch_bounds__(256) void k_softmax(float* __restrict__ S) {
    size_t base = (size_t)blockIdx.x * SEQ;
    int t = threadIdx.x;
    float v[8];
    float mx = -3.4e38f;
    #pragma unroll
    for (int i = 0; i < 8; i++) { v[i] = S[base + t + i * 256]; mx = fmaxf(mx, v[i]); }
    __shared__ float sh[8];
    #pragma unroll
    for (int o = 16; o; o >>= 1) mx = fmaxf(mx, __shfl_xor_sync(0xffffffffu, mx, o));
    if ((t & 31) == 0) sh[t >> 5] = mx;
    __syncthreads();
    mx = sh[0];
    #pragma unroll
    for (int w = 1; w < 8; w++) mx = fmaxf(mx, sh[w]);
    __syncthreads();
    float s = 0.f;
    #pragma unroll
    for (int i = 0; i < 8; i++) { v[i] = __expf(v[i] - mx); s += v[i]; }
    s = warpSum(s);
    if ((t & 31) == 0) sh[t >> 5] = s;
    __syncthreads();
    s = 0.f;
    #pragma unroll
    for (int w = 0; w < 8; w++) s += sh[w];
    float r = 1.f / s;
    #pragma unroll
    for (int i = 0; i < 8; i++) S[base + t + i * 256] = f2tf32f(v[i] * r);
}

// ---------------- launch ----------------
extern "C" void kernel_launch(void* const* d_in, const int* in_sizes, int n_in,
                              void* d_out, int out_size) {
    const float* x   = (const float*)d_in[0];
    const float* vec = (const float*)d_in[1];
    const float* pe  = (const float*)d_in[2];
    const float* w1  = (const float*)d_in[3];
    const float* b1  = (const float*)d_in[4];
    const float* w2  = (const float*)d_in[5];
    const float* b2  = (const float*)d_in[6];
    const float* mw  = (const float*)d_in[7];
    const float* mb  = (const float*)d_in[8];
    const float* qw  = (const float*)d_in[9];
    const float* kw  = (const float*)d_in[10];
    float* out = (float*)d_out;

    float *p_mod, *p_xmod, *p_h, *p_qr, *p_kr, *p_sc, *p_a2, *p_w1t, *p_w2t;
    cudaGetSymbolAddress((void**)&p_mod,  g_mod);
    cudaGetSymbolAddress((void**)&p_xmod, g_xmod);
    cudaGetSymbolAddress((void**)&p_h,    g_h);
    cudaGetSymbolAddress((void**)&p_qr,   g_qr);
    cudaGetSymbolAddress((void**)&p_kr,   g_kr);
    cudaGetSymbolAddress((void**)&p_sc,   g_sc);
    cudaGetSymbolAddress((void**)&p_a2,   g_a2);
    cudaGetSymbolAddress((void**)&p_w1t,  g_w1t);
    cudaGetSymbolAddress((void**)&p_w2t,  g_w2t);

    // dynamic smem sizes: NS*(BM*AP + BROW*BCOL)*4
    const int SM_NN = 4 * (128 * 20 + 16 * 136) * 4;   // 75776 B
    const int SM_TN = 4 * (128 * 20 + 128 * 20) * 4;   // 81920 B
    cudaFuncSetAttribute(mma_gemm<1, false>,
        cudaFuncAttributeMaxDynamicSharedMemorySize, SM_NN);
    cudaFuncSetAttribute(mma_gemm<3, false>,
        cudaFuncAttributeMaxDynamicSharedMemorySize, SM_NN);
    cudaFuncSetAttribute(mma_gemm<0, false>,
        cudaFuncAttributeMaxDynamicSharedMemorySize, SM_NN);
    cudaFuncSetAttribute(mma_gemm<2, false>,
        cudaFuncAttributeMaxDynamicSharedMemorySize, SM_NN);
    cudaFuncSetAttribute(mma_gemm<0, true>,
        cudaFuncAttributeMaxDynamicSharedMemorySize, SM_TN);

    // 0) pre-round weights to tf32 (once per launch)
    k_cvt<<<(size_t)HID * W1N / 1024, 256>>>(w1, p_w1t);
    k_cvt<<<(size_t)A2N * HID / 1024, 256>>>(w2, p_w2t);
    // 1) modulation vector
    k_mod<<<MODN / 256, 256>>>(vec, mw, mb);
    // 2) layernorm + modulate (tf32-rounded)
    k_lnmod<<<SEQ, 256>>>(x);
    // 3a) qkv = x_mod @ w1[:, :9216] + b1  -> g_h
    {
        dim3 g(3 * HID / 128, SEQ / 128, 1);
        mma_gemm<1, false><<<g, 128, SM_NN>>>(HID,
            p_xmod, HID, 0, p_w1t, W1N, 0, p_h, W1N, 0, b1, nullptr, nullptr);
    }
    // 3b) gelu(x_mod @ w1[:, 9216:] + b1') -> g_a2 cols [3072, 15360)
    {
        dim3 g(MLP / 128, SEQ / 128, 1);
        mma_gemm<3, false><<<g, 128, SM_NN>>>(HID,
            p_xmod, HID, 0, p_w1t + 3 * HID, W1N, 0,
            p_a2 + HID, A2N, 0, b1 + 3 * HID, nullptr, nullptr);
    }
    // 4) q/k rmsnorm + rope (scale folded into q, tf32-rounded)
    k_qk<<<(SEQ * NH * 32) / 256, 256>>>(pe, qw, kw);
    // 5) scores = q @ k^T, per head   (tf32, B transposed)
    {
        dim3 g(SEQ / 128, SEQ / 128, NH);
        mma_gemm<0, true><<<g, 128, SM_TN>>>(HD,
            p_qr, HID, HD, p_kr, HID, HD, p_sc, SEQ, (long long)SEQ * SEQ,
            nullptr, nullptr, nullptr);
    }
    // 6) softmax over keys (tf32-rounded)
    k_softmax<<<NH * SEQ, 256>>>(p_sc);
    // 7) attn = P @ V  -> g_a2 columns [0, 3072)
    {
        dim3 g(1, SEQ / 128, NH);
        mma_gemm<0, false><<<g, 128, SM_NN>>>(SEQ,
            p_sc, SEQ, (long long)SEQ * SEQ,
            p_h + 2 * HID, W1N, HD,
            p_a2, A2N, HD, nullptr, nullptr, nullptr);
    }
    // 8) out = x + gate * ([attn | gelu(mlp)] @ w2 + b2)   (tf32)
    {
        dim3 g(HID / 128, SEQ / 128, 1);
        mma_gemm<2, false><<<g, 128, SM_NN>>>(A2N,
            p_a2, A2N, 0, p_w2t, HID, 0, out, HID, 0, b2, x, p_mod + 2 * HID);
    }
}